// round 14
// baseline (speedup 1.0000x reference)
#include <cuda_runtime.h>
#include <math.h>

#define D_MODEL 256
#define NHEAD 8
#define DHEAD 32
#define D_FF 1024
#define N_BLOCKS 2
#define BATCH 256
#define INTER 50
#define INTRA 20
#define CAND 2048
#define NTOK (BATCH*INTER)
#define NEG_INF -1.0e9f

// ---------------- scratch (device globals; allocation-free) ----------------
__device__ __align__(256) float g_Ehat[NTOK*D_MODEL];
__device__ __align__(256) float g_S [NTOK*D_MODEL];
__device__ __align__(256) float g_Yb [NTOK*D_MODEL];     // final LN (plain)
__device__ __align__(256) float g_Yh [NTOK*D_MODEL];     // ln hi/lo planes
__device__ __align__(256) float g_Yl [NTOK*D_MODEL];
__device__ __align__(256) float g_Qb [NTOK*D_MODEL];
__device__ __align__(256) float g_Kb [NTOK*D_MODEL];
__device__ __align__(256) float g_Vb [NTOK*D_MODEL];
__device__ __align__(256) float g_Th [NTOK*D_MODEL];     // attn out planes
__device__ __align__(256) float g_Tl [NTOK*D_MODEL];
__device__ __align__(256) float g_Hh [NTOK*D_FF];        // ffn hidden planes
__device__ __align__(256) float g_Hl [NTOK*D_FF];
__device__ __align__(256) float g_ushort[BATCH*D_MODEL];
__device__ __align__(256) float g_ulong [BATCH*D_MODEL];
__device__ __align__(256) float g_Ugate [BATCH*D_MODEL];
// transposed tf32 weight planes [N][K]
__device__ __align__(256) float g_Whq[D_MODEL*D_MODEL];  __device__ __align__(256) float g_Wlq[D_MODEL*D_MODEL];
__device__ __align__(256) float g_Whk[D_MODEL*D_MODEL];  __device__ __align__(256) float g_Wlk[D_MODEL*D_MODEL];
__device__ __align__(256) float g_Whv[D_MODEL*D_MODEL];  __device__ __align__(256) float g_Wlv[D_MODEL*D_MODEL];
__device__ __align__(256) float g_Who[D_MODEL*D_MODEL];  __device__ __align__(256) float g_Wlo[D_MODEL*D_MODEL];
__device__ __align__(256) float g_Wh1[D_MODEL*D_FF];     __device__ __align__(256) float g_Wl1[D_MODEL*D_FF];
__device__ __align__(256) float g_Wh2[D_FF*D_MODEL];     __device__ __align__(256) float g_Wl2[D_FF*D_MODEL];

// ---------------- tf32 / mma / cp.async helpers ----------------
__device__ __forceinline__ unsigned f2tf32(float f) {
    unsigned u; asm("cvt.rna.tf32.f32 %0, %1;" : "=r"(u) : "f"(f)); return u;
}
__device__ __forceinline__ void split_tf32(float v, float &hi, float &lo) {
    unsigned h = f2tf32(v);
    hi = __uint_as_float(h);
    lo = __uint_as_float(f2tf32(v - hi));
}
__device__ __forceinline__ void mma_tf32(float* c,
    unsigned a0, unsigned a1, unsigned a2, unsigned a3,
    unsigned b0, unsigned b1) {
    asm volatile("mma.sync.aligned.m16n8k8.row.col.f32.tf32.tf32.f32 "
        "{%0,%1,%2,%3}, {%4,%5,%6,%7}, {%8,%9}, {%0,%1,%2,%3};"
        : "+f"(c[0]), "+f"(c[1]), "+f"(c[2]), "+f"(c[3])
        : "r"(a0), "r"(a1), "r"(a2), "r"(a3), "r"(b0), "r"(b1));
}
__device__ __forceinline__ void cp16(void* smem, const void* g) {
    unsigned s = (unsigned)__cvta_generic_to_shared(smem);
    asm volatile("cp.async.cg.shared.global [%0], [%1], 16;" :: "r"(s), "l"(g));
}
__device__ __forceinline__ void cp_commit() {
    asm volatile("cp.async.commit_group;" ::: "memory");
}
__device__ __forceinline__ void cp_wait0() {
    asm volatile("cp.async.wait_group 0;" ::: "memory");
}

// ---------------- weight transpose + tf32 hi/lo split: W[K][N] -> Wh/Wl[N][K] ----------------
__global__ __launch_bounds__(256) void transpose_split(const float* __restrict__ W,
                                                       float* __restrict__ Wh,
                                                       float* __restrict__ Wl,
                                                       int Kd, int Nd) {
    __shared__ float tile[32][33];
    const int n0 = blockIdx.x*32, k0 = blockIdx.y*32;
    const int tx = threadIdx.x & 31, ty = threadIdx.x >> 5;
    #pragma unroll
    for (int i = 0; i < 4; i++) {
        int r = ty + i*8;
        tile[r][tx] = W[(size_t)(k0+r)*Nd + n0 + tx];
    }
    __syncthreads();
    #pragma unroll
    for (int i = 0; i < 4; i++) {
        int r = ty + i*8;
        float hi, lo; split_tf32(tile[tx][r], hi, lo);
        Wh[(size_t)(n0+r)*Kd + k0 + tx] = hi;
        Wl[(size_t)(n0+r)*Kd + k0 + tx] = lo;
    }
}

// ---------------- 3xTF32 plane GEMM: C = A@W + bias (+relu-split | +res) ----------------
// CTA MT(M)x64(N), 128 threads (2x2 warps), warp tile (MT/2)x32, BK=16,
// cp.async double buffer. A planes Ah/Al [M][K], W planes [N][K]; no cvt in loop.
// MODE 0: bias, plain out (z selects weight/bias/out triple)
// MODE 1: bias+relu, out split into Ca(hi)/Cb(lo)
// MODE 2: bias+residual, plain out
template<int MODE, int MT>
__global__ __launch_bounds__(128) void tf32gemm2(
    const float* __restrict__ Ah, const float* __restrict__ Al,
    const float* __restrict__ Wha, const float* __restrict__ Wla,
    const float* __restrict__ Whb, const float* __restrict__ Wlb,
    const float* __restrict__ Whc, const float* __restrict__ Wlc,
    const float* __restrict__ ba,  const float* __restrict__ bb,  const float* __restrict__ bc,
    float* __restrict__ Ca, float* __restrict__ Cb, float* __restrict__ Cc,
    const float* __restrict__ res, int M, int N, int K) {
    __shared__ float sAh[2][MT][20], sAl[2][MT][20];
    __shared__ float sBh[2][64][20], sBl[2][64][20];

    const float* Wh = Wha; const float* Wl = Wla; const float* bias = ba; float* C = Ca;
    if (MODE == 0) {
        if (blockIdx.z == 1) { Wh = Whb; Wl = Wlb; bias = bb; C = Cb; }
        else if (blockIdx.z == 2) { Wh = Whc; Wl = Wlc; bias = bc; C = Cc; }
    }

    const int t = threadIdx.x;
    const int wid = t >> 5, lane = t & 31;
    const int wm = wid & 1, wn = wid >> 1;
    const int gid = lane >> 2, tig = lane & 3;
    const int bm = blockIdx.y * MT, bn = blockIdx.x * 64;
    constexpr int MTW = MT / 32;       // m16 tiles per warp

    float acc[MTW][4][4];
    #pragma unroll
    for (int i = 0; i < MTW; i++)
        #pragma unroll
        for (int j = 0; j < 4; j++)
            #pragma unroll
            for (int k = 0; k < 4; k++) acc[i][j][k] = 0.f;

    const int nKB = K >> 4;
    // load helper: A tasks MT*4, B tasks 256
    auto issue = [&](int buf, int k0) {
        #pragma unroll
        for (int i = 0; i < MT/32; i++) {
            int id = t + 128*i, r = id >> 2, ch = id & 3;
            cp16(&sAh[buf][r][ch*4], Ah + (size_t)(bm+r)*K + k0 + ch*4);
            cp16(&sAl[buf][r][ch*4], Al + (size_t)(bm+r)*K + k0 + ch*4);
        }
        #pragma unroll
        for (int i = 0; i < 2; i++) {
            int id = t + 128*i, r = id >> 2, ch = id & 3;
            cp16(&sBh[buf][r][ch*4], Wh + (size_t)(bn+r)*K + k0 + ch*4);
            cp16(&sBl[buf][r][ch*4], Wl + (size_t)(bn+r)*K + k0 + ch*4);
        }
        cp_commit();
    };

    issue(0, 0);
    for (int kb = 0; kb < nKB; kb++) {
        const int cur = kb & 1;
        cp_wait0();
        __syncthreads();
        if (kb + 1 < nKB) issue(cur ^ 1, (kb+1)*16);
        #pragma unroll
        for (int jj = 0; jj < 2; jj++) {
            unsigned ah[MTW][4], al[MTW][4], bh[4][2], bl[4][2];
            #pragma unroll
            for (int mt = 0; mt < MTW; mt++) {
                int r = wm*(MT/2) + mt*16 + gid;
                ah[mt][0] = __float_as_uint(sAh[cur][r  ][jj*8 + tig]);
                ah[mt][1] = __float_as_uint(sAh[cur][r+8][jj*8 + tig]);
                ah[mt][2] = __float_as_uint(sAh[cur][r  ][jj*8 + 4 + tig]);
                ah[mt][3] = __float_as_uint(sAh[cur][r+8][jj*8 + 4 + tig]);
                al[mt][0] = __float_as_uint(sAl[cur][r  ][jj*8 + tig]);
                al[mt][1] = __float_as_uint(sAl[cur][r+8][jj*8 + tig]);
                al[mt][2] = __float_as_uint(sAl[cur][r  ][jj*8 + 4 + tig]);
                al[mt][3] = __float_as_uint(sAl[cur][r+8][jj*8 + 4 + tig]);
            }
            #pragma unroll
            for (int nt = 0; nt < 4; nt++) {
                int n = wn*32 + nt*8 + gid;
                bh[nt][0] = __float_as_uint(sBh[cur][n][jj*8 + tig]);
                bh[nt][1] = __float_as_uint(sBh[cur][n][jj*8 + 4 + tig]);
                bl[nt][0] = __float_as_uint(sBl[cur][n][jj*8 + tig]);
                bl[nt][1] = __float_as_uint(sBl[cur][n][jj*8 + 4 + tig]);
            }
            #pragma unroll
            for (int mt = 0; mt < MTW; mt++)
                #pragma unroll
                for (int nt = 0; nt < 4; nt++) {
                    mma_tf32(acc[mt][nt], al[mt][0], al[mt][1], al[mt][2], al[mt][3],
                             bh[nt][0], bh[nt][1]);
                    mma_tf32(acc[mt][nt], ah[mt][0], ah[mt][1], ah[mt][2], ah[mt][3],
                             bl[nt][0], bl[nt][1]);
                    mma_tf32(acc[mt][nt], ah[mt][0], ah[mt][1], ah[mt][2], ah[mt][3],
                             bh[nt][0], bh[nt][1]);
                }
        }
        __syncthreads();
    }

    // epilogue
    #pragma unroll
    for (int nt = 0; nt < 4; nt++) {
        const int col = bn + wn*32 + nt*8 + 2*tig;
        const float2 bb2 = *(const float2*)(bias + col);
        #pragma unroll
        for (int mt = 0; mt < MTW; mt++) {
            #pragma unroll
            for (int h = 0; h < 2; h++) {
                const int row = bm + wm*(MT/2) + mt*16 + gid + h*8;
                float v0 = acc[mt][nt][h*2+0] + bb2.x;
                float v1 = acc[mt][nt][h*2+1] + bb2.y;
                if (MODE == 1) {
                    v0 = fmaxf(v0, 0.f); v1 = fmaxf(v1, 0.f);
                    float h0, l0, h1, l1;
                    split_tf32(v0, h0, l0); split_tf32(v1, h1, l1);
                    float2 oh; oh.x = h0; oh.y = h1;
                    float2 ol; ol.x = l0; ol.y = l1;
                    *(float2*)(Ca + (size_t)row*N + col) = oh;
                    *(float2*)(Cb + (size_t)row*N + col) = ol;
                } else {
                    if (MODE == 2) {
                        float2 r2 = *(const float2*)(res + (size_t)row*N + col);
                        v0 += r2.x; v1 += r2.y;
                    }
                    float2 o; o.x = v0; o.y = v1;
                    *(float2*)(C + (size_t)row*N + col) = o;
                }
            }
        }
    }
}

// ---------------- intra-session attention -> E_hat ----------------
__global__ __launch_bounds__(128) void intra_kernel(const float* __restrict__ item_emb,
                                                    const int* __restrict__ sessions) {
    __shared__ float x[INTRA][260];
    __shared__ float sc[INTRA][INTRA+1];
    __shared__ float wsum[INTRA];
    __shared__ int   idxs[INTRA];
    const int n = blockIdx.x;
    const int t = threadIdx.x;

    if (t < INTRA) idxs[t] = sessions[n*INTRA + t];
    __syncthreads();

    for (int j = t; j < INTRA*64; j += 128) {
        int r = j >> 6, c = j & 63;
        float4 v = make_float4(0.f,0.f,0.f,0.f);
        int idx = idxs[r];
        if (idx != 0) v = *(const float4*)(item_emb + (size_t)idx*D_MODEL + c*4);
        *(float4*)&x[r][c*4] = v;
    }
    __syncthreads();

    if (t < 80) {
        const int qp = t >> 3, c = t & 7;
        const unsigned mask = (t >= 64) ? 0x0000ffffu : 0xffffffffu;
        float4 qA[8], qB[8];
        #pragma unroll
        for (int i = 0; i < 8; i++) {
            qA[i] = *(const float4*)&x[2*qp  ][c*32 + i*4];
            qB[i] = *(const float4*)&x[2*qp+1][c*32 + i*4];
        }
        for (int k = 0; k < INTRA; k++) {
            float sa = 0.f, sb = 0.f;
            #pragma unroll
            for (int i = 0; i < 8; i++) {
                float4 bv = *(const float4*)&x[k][c*32 + i*4];
                sa += qA[i].x*bv.x + qA[i].y*bv.y + qA[i].z*bv.z + qA[i].w*bv.w;
                sb += qB[i].x*bv.x + qB[i].y*bv.y + qB[i].z*bv.z + qB[i].w*bv.w;
            }
            sa += __shfl_xor_sync(mask, sa, 1);
            sa += __shfl_xor_sync(mask, sa, 2);
            sa += __shfl_xor_sync(mask, sa, 4);
            sb += __shfl_xor_sync(mask, sb, 1);
            sb += __shfl_xor_sync(mask, sb, 2);
            sb += __shfl_xor_sync(mask, sb, 4);
            if (c == 0) {
                sc[2*qp  ][k] = sa * 0.0625f;
                sc[2*qp+1][k] = sb * 0.0625f;
            }
        }
    }
    __syncthreads();

    if (t < INTRA) {
        float v[INTRA];
        float mx = -3.0e38f;
        #pragma unroll
        for (int k = 0; k < INTRA; k++) {
            float s = (idxs[k] != 0) ? sc[t][k] : NEG_INF;
            v[k] = s; mx = fmaxf(mx, s);
        }
        float sum = 0.f;
        #pragma unroll
        for (int k = 0; k < INTRA; k++) { float e = __expf(v[k]-mx); v[k] = e; sum += e; }
        float inv = 1.f/sum;
        #pragma unroll
        for (int k = 0; k < INTRA; k++) sc[t][k] = v[k]*inv;
    }
    __syncthreads();

    if (t < INTRA) {
        float w = 0.f;
        #pragma unroll
        for (int q = 0; q < INTRA; q++) w += sc[q][t];
        wsum[t] = w;
    }
    __syncthreads();

    float* outp = g_Ehat + (size_t)n*D_MODEL;
    for (int d = t; d < D_MODEL; d += 128) {
        float acc = 0.f;
        #pragma unroll
        for (int k = 0; k < INTRA; k++) acc += wsum[k]*x[k][d];
        outp[d] = acc;
    }
}

// ---------------- S = E_hat + PE ; u_short ----------------
__global__ __launch_bounds__(256) void initS_kernel() {
    int i = blockIdx.x*256 + threadIdx.x;
    int d = i & 255;
    int tok = i >> 8;
    int pos = tok % INTER;
    int j = d >> 1;
    float div = expf((float)(2*j) * (-0.03597789207803197f));
    float ang = (float)pos * div;
    float pe = (d & 1) ? cosf(ang) : sinf(ang);
    float eh = g_Ehat[i];
    g_S[i] = eh + pe;
    if (pos == INTER-1) g_ushort[(tok/INTER)*D_MODEL + d] = eh;
}

// ---------------- LayerNorm; SPLIT=1 writes tf32 hi/lo planes ----------------
template<int SPLIT>
__global__ __launch_bounds__(256) void ln_kernel(const float* __restrict__ x,
                                                 float* __restrict__ y, float* __restrict__ ylo,
                                                 const float* __restrict__ g, const float* __restrict__ b) {
    const int tok  = blockIdx.x*8 + (threadIdx.x >> 5);
    const int lane = threadIdx.x & 31;
    const float4* xr = (const float4*)(x + (size_t)tok*D_MODEL);
    float4 a = xr[lane*2], c = xr[lane*2+1];
    float s  = a.x+a.y+a.z+a.w + c.x+c.y+c.z+c.w;
    float ss = a.x*a.x+a.y*a.y+a.z*a.z+a.w*a.w + c.x*c.x+c.y*c.y+c.z*c.z+c.w*c.w;
    #pragma unroll
    for (int o = 16; o > 0; o >>= 1) {
        s  += __shfl_xor_sync(0xffffffffu, s , o);
        ss += __shfl_xor_sync(0xffffffffu, ss, o);
    }
    float m   = s * (1.f/256.f);
    float var = fmaxf((ss - 256.f*m*m) * (1.f/255.f), 0.f);
    float inv = 1.f/(sqrtf(var) + 1e-6f);
    float4 g0 = ((const float4*)g)[lane*2], g1 = ((const float4*)g)[lane*2+1];
    float4 b0 = ((const float4*)b)[lane*2], b1 = ((const float4*)b)[lane*2+1];
    float4 o0, o1;
    o0.x = g0.x*(a.x-m)*inv + b0.x;  o0.y = g0.y*(a.y-m)*inv + b0.y;
    o0.z = g0.z*(a.z-m)*inv + b0.z;  o0.w = g0.w*(a.w-m)*inv + b0.w;
    o1.x = g1.x*(c.x-m)*inv + b1.x;  o1.y = g1.y*(c.y-m)*inv + b1.y;
    o1.z = g1.z*(c.z-m)*inv + b1.z;  o1.w = g1.w*(c.w-m)*inv + b1.w;
    if (SPLIT) {
        float4 h0, l0, h1, l1;
        split_tf32(o0.x, h0.x, l0.x); split_tf32(o0.y, h0.y, l0.y);
        split_tf32(o0.z, h0.z, l0.z); split_tf32(o0.w, h0.w, l0.w);
        split_tf32(o1.x, h1.x, l1.x); split_tf32(o1.y, h1.y, l1.y);
        split_tf32(o1.z, h1.z, l1.z); split_tf32(o1.w, h1.w, l1.w);
        float4* yh = (float4*)(y   + (size_t)tok*D_MODEL);
        float4* yl = (float4*)(ylo + (size_t)tok*D_MODEL);
        yh[lane*2] = h0; yh[lane*2+1] = h1;
        yl[lane*2] = l0; yl[lane*2+1] = l1;
    } else {
        float4* yr = (float4*)(y + (size_t)tok*D_MODEL);
        yr[lane*2] = o0; yr[lane*2+1] = o1;
    }
}

// ---------------- inter attention: per (batch, head), hi/lo plane output ----------------
__global__ __launch_bounds__(128) void attn_kernel(const int* __restrict__ sessions) {
    const int b = blockIdx.x, h = blockIdx.y;
    __shared__ float ks[INTER][36];
    __shared__ float vs[INTER][36];
    __shared__ float sc[INTER][53];
    __shared__ int   valid[INTER];
    const int t = threadIdx.x;

    if (t < INTER) valid[t] = sessions[(size_t)(b*INTER + t)*INTRA];
    const float* Kb = g_Kb + (size_t)b*INTER*D_MODEL + h*DHEAD;
    const float* Vb = g_Vb + (size_t)b*INTER*D_MODEL + h*DHEAD;
    for (int j = t; j < INTER*8; j += 128) {
        int r = j >> 3, c = j & 7;
        *(float4*)&ks[r][c*4] = *(const float4*)(Kb + (size_t)r*D_MODEL + c*4);
        *(float4*)&vs[r][c*4] = *(const float4*)(Vb + (size_t)r*D_MODEL + c*4);
    }
    __syncthreads();

    if (t < INTER) {
        const float* Qr = g_Qb + (size_t)(b*INTER + t)*D_MODEL + h*DHEAD;
        float4 q[8];
        #pragma unroll
        for (int i = 0; i < 8; i++) q[i] = *(const float4*)(Qr + i*4);
        float mx = -3.0e38f;
        for (int k = 0; k < INTER; k++) {
            float s = 0.f;
            #pragma unroll
            for (int i = 0; i < 8; i++) {
                float4 kv = *(const float4*)&ks[k][i*4];
                s += q[i].x*kv.x + q[i].y*kv.y + q[i].z*kv.z + q[i].w*kv.w;
            }
            s = (valid[k] != 0) ? s*0.17677669529663688f : NEG_INF;
            sc[t][k] = s; mx = fmaxf(mx, s);
        }
        float sum = 0.f;
        for (int k = 0; k < INTER; k++) { float e = __expf(sc[t][k]-mx); sc[t][k] = e; sum += e; }
        float inv = 1.f/sum;
        for (int k = 0; k < INTER; k++) sc[t][k] *= inv;
    }
    __syncthreads();

    float* Oh = g_Th + (size_t)b*INTER*D_MODEL + h*DHEAD;
    float* Ol = g_Tl + (size_t)b*INTER*D_MODEL + h*DHEAD;
    for (int e = t; e < INTER*DHEAD; e += 128) {
        int q = e >> 5, d = e & 31;
        float acc = 0.f;
        #pragma unroll 10
        for (int k = 0; k < INTER; k++) acc += sc[q][k]*vs[k][d];
        float hi, lo; split_tf32(acc, hi, lo);
        Oh[(size_t)q*D_MODEL + d] = hi;
        Ol[(size_t)q*D_MODEL + d] = lo;
    }
}

// ---------------- u_long ----------------
__global__ __launch_bounds__(256) void ulong_kernel(const float* __restrict__ user_emb,
                                                    const int* __restrict__ us) {
    const int b = blockIdx.x, d = threadIdx.x;
    float acc = 0.f;
    const float* Yb = g_Yb + (size_t)b*INTER*D_MODEL + d;
    #pragma unroll 10
    for (int i = 0; i < INTER; i++) acc += Yb[(size_t)i*D_MODEL];
    g_ulong[b*D_MODEL + d] = acc + user_emb[(size_t)us[b]*D_MODEL + d];
}

// ---------------- gate + fuse ----------------
__global__ __launch_bounds__(256) void gate_kernel(
    const float* __restrict__ Wl, const float* __restrict__ Ws,
    const float* __restrict__ Wt, const float* __restrict__ gb,
    const float* __restrict__ time_emb, const int* __restrict__ tdl) {
    __shared__ float ul[8][260], uss[8][260], te[8][260];
    const int t = threadIdx.x;
    const int b0 = blockIdx.x*8;
    for (int j = t; j < 8*64; j += 256) {
        int bi = j >> 6, c = j & 63;
        *(float4*)&ul [bi][c*4] = *(const float4*)(g_ulong  + (size_t)(b0+bi)*D_MODEL + c*4);
        *(float4*)&uss[bi][c*4] = *(const float4*)(g_ushort + (size_t)(b0+bi)*D_MODEL + c*4);
        *(float4*)&te [bi][c*4] = *(const float4*)(time_emb + (size_t)tdl[b0+bi]*D_MODEL + c*4);
    }
    __syncthreads();
    const int d = t;
    float acc[8] = {0.f,0.f,0.f,0.f,0.f,0.f,0.f,0.f};
    for (int k = 0; k < D_MODEL; k++) {
        float wl = Wl[(size_t)k*D_MODEL + d];
        float ws = Ws[(size_t)k*D_MODEL + d];
        float wt = Wt[(size_t)k*D_MODEL + d];
        #pragma unroll
        for (int bi = 0; bi < 8; bi++)
            acc[bi] += ul[bi][k]*wl + uss[bi][k]*ws + te[bi][k]*wt;
    }
    float gbv = gb[d];
    #pragma unroll
    for (int bi = 0; bi < 8; bi++) {
        float z  = acc[bi] + gbv;
        float tg = 1.f/(1.f + expf(-z));
        g_Ugate[(size_t)(b0+bi)*D_MODEL + d] = tg*uss[bi][d] + (1.f-tg)*ul[bi][d];
    }
}

// ---------------- candidate scoring ----------------
__global__ __launch_bounds__(256) void score_kernel(const float* __restrict__ item_emb,
                                                    const int* __restrict__ pred,
                                                    float* __restrict__ out) {
    const int b = blockIdx.x;
    const int warp = threadIdx.x >> 5, lane = threadIdx.x & 31;
    const int wg = blockIdx.y*8 + warp;
    const float4* up = (const float4*)(g_Ugate + (size_t)b*D_MODEL);
    float4 ua = up[lane*2], ub = up[lane*2+1];
    const int cbase = b*CAND;
    for (int c0 = wg*64; c0 < wg*64 + 64; c0 += 2) {
        int i0 = pred[cbase + c0];
        int i1 = pred[cbase + c0 + 1];
        const float4* r0 = (const float4*)(item_emb + (size_t)i0*D_MODEL);
        const float4* r1 = (const float4*)(item_emb + (size_t)i1*D_MODEL);
        float4 a0 = r0[lane*2], b0 = r0[lane*2+1];
        float4 a1 = r1[lane*2], b1 = r1[lane*2+1];
        float s0 = a0.x*ua.x + a0.y*ua.y + a0.z*ua.z + a0.w*ua.w
                 + b0.x*ub.x + b0.y*ub.y + b0.z*ub.z + b0.w*ub.w;
        float s1 = a1.x*ua.x + a1.y*ua.y + a1.z*ua.z + a1.w*ua.w
                 + b1.x*ub.x + b1.y*ub.y + b1.z*ub.z + b1.w*ub.w;
        #pragma unroll
        for (int o = 16; o > 0; o >>= 1) {
            s0 += __shfl_xor_sync(0xffffffffu, s0, o);
            s1 += __shfl_xor_sync(0xffffffffu, s1, o);
        }
        if (lane == 0) {
            out[(size_t)cbase + c0]     = s0;
            out[(size_t)cbase + c0 + 1] = s1;
        }
    }
}

// ---------------- launcher ----------------
extern "C" void kernel_launch(void* const* d_in, const int* in_sizes, int n_in,
                              void* d_out, int out_size) {
    (void)in_sizes; (void)n_in; (void)out_size;
    const float* item_emb = (const float*)d_in[0];
    const float* user_emb = (const float*)d_in[1];
    const float* time_emb = (const float*)d_in[2];
    const float* Wq = (const float*)d_in[3];   const float* bq = (const float*)d_in[4];
    const float* Wk = (const float*)d_in[5];   const float* bk = (const float*)d_in[6];
    const float* Wv = (const float*)d_in[7];   const float* bv = (const float*)d_in[8];
    const float* Wo = (const float*)d_in[9];   const float* bo = (const float*)d_in[10];
    const float* ln1_g = (const float*)d_in[11]; const float* ln1_b = (const float*)d_in[12];
    const float* W1 = (const float*)d_in[13];  const float* b1 = (const float*)d_in[14];
    const float* W2 = (const float*)d_in[15];  const float* b2 = (const float*)d_in[16];
    const float* ln2_g = (const float*)d_in[17]; const float* ln2_b = (const float*)d_in[18];
    const float* fn_g  = (const float*)d_in[19]; const float* fn_b  = (const float*)d_in[20];
    const float* gWl = (const float*)d_in[21]; const float* gWs = (const float*)d_in[22];
    const float* gWt = (const float*)d_in[23]; const float* gbias = (const float*)d_in[24];
    const int* us   = (const int*)d_in[25];
    const int* sess = (const int*)d_in[26];
    const int* tdl  = (const int*)d_in[27];
    const int* pred = (const int*)d_in[28];
    float* out = (float*)d_out;

    float *pS, *pY, *pYh, *pYl, *pQ, *pK, *pV, *pTh, *pTl, *pHh, *pHl;
    float *pWhq,*pWlq,*pWhk,*pWlk,*pWhv,*pWlv,*pWho,*pWlo,*pWh1,*pWl1,*pWh2,*pWl2;
    cudaGetSymbolAddress((void**)&pS,  g_S);
    cudaGetSymbolAddress((void**)&pY,  g_Yb);
    cudaGetSymbolAddress((void**)&pYh, g_Yh);
    cudaGetSymbolAddress((void**)&pYl, g_Yl);
    cudaGetSymbolAddress((void**)&pQ,  g_Qb);
    cudaGetSymbolAddress((void**)&pK,  g_Kb);
    cudaGetSymbolAddress((void**)&pV,  g_Vb);
    cudaGetSymbolAddress((void**)&pTh, g_Th);
    cudaGetSymbolAddress((void**)&pTl, g_Tl);
    cudaGetSymbolAddress((void**)&pHh, g_Hh);
    cudaGetSymbolAddress((void**)&pHl, g_Hl);
    cudaGetSymbolAddress((void**)&pWhq, g_Whq); cudaGetSymbolAddress((void**)&pWlq, g_Wlq);
    cudaGetSymbolAddress((void**)&pWhk, g_Whk); cudaGetSymbolAddress((void**)&pWlk, g_Wlk);
    cudaGetSymbolAddress((void**)&pWhv, g_Whv); cudaGetSymbolAddress((void**)&pWlv, g_Wlv);
    cudaGetSymbolAddress((void**)&pWho, g_Who); cudaGetSymbolAddress((void**)&pWlo, g_Wlo);
    cudaGetSymbolAddress((void**)&pWh1, g_Wh1); cudaGetSymbolAddress((void**)&pWl1, g_Wl1);
    cudaGetSymbolAddress((void**)&pWh2, g_Wh2); cudaGetSymbolAddress((void**)&pWl2, g_Wl2);

    // one-time (per launch) weight transpose + hi/lo split
    transpose_split<<<dim3(8,8),  256>>>(Wq, pWhq, pWlq, D_MODEL, D_MODEL);
    transpose_split<<<dim3(8,8),  256>>>(Wk, pWhk, pWlk, D_MODEL, D_MODEL);
    transpose_split<<<dim3(8,8),  256>>>(Wv, pWhv, pWlv, D_MODEL, D_MODEL);
    transpose_split<<<dim3(8,8),  256>>>(Wo, pWho, pWlo, D_MODEL, D_MODEL);
    transpose_split<<<dim3(32,8), 256>>>(W1, pWh1, pWl1, D_MODEL, D_FF);
    transpose_split<<<dim3(8,32), 256>>>(W2, pWh2, pWl2, D_FF, D_MODEL);

    intra_kernel<<<NTOK, 128>>>(item_emb, sess);
    initS_kernel<<<NTOK*D_MODEL/256, 256>>>();

    const dim3 gQKV(D_MODEL/64, NTOK/64, 3);   // (4, 40, 3) MT=64
    const dim3 gO  (D_MODEL/64, NTOK/32, 1);   // (4, 80)    MT=32
    const dim3 gF1 (D_FF/64,   NTOK/64, 1);    // (16, 40)   MT=64
    const dim3 gF2 (D_MODEL/64, NTOK/32, 1);   // (4, 80)    MT=32

    for (int blk = 0; blk < N_BLOCKS; blk++) {
        ln_kernel<1><<<NTOK/8, 256>>>(pS, pYh, pYl, ln1_g, ln1_b);
        tf32gemm2<0,64><<<gQKV, 128>>>(pYh, pYl,
                                       pWhq, pWlq, pWhk, pWlk, pWhv, pWlv,
                                       bq, bk, bv, pQ, pK, pV,
                                       nullptr, NTOK, D_MODEL, D_MODEL);
        attn_kernel<<<dim3(BATCH, NHEAD), 128>>>(sess);
        tf32gemm2<2,32><<<gO, 128>>>(pTh, pTl,
                                     pWho, pWlo, pWho, pWlo, pWho, pWlo,
                                     bo, bo, bo, pS, pS, pS,
                                     pS, NTOK, D_MODEL, D_MODEL);
        ln_kernel<1><<<NTOK/8, 256>>>(pS, pYh, pYl, ln2_g, ln2_b);
        tf32gemm2<1,64><<<gF1, 128>>>(pYh, pYl,
                                      pWh1, pWl1, pWh1, pWl1, pWh1, pWl1,
                                      b1, b1, b1, pHh, pHl, pHh,
                                      nullptr, NTOK, D_FF, D_MODEL);
        tf32gemm2<2,32><<<gF2, 128>>>(pHh, pHl,
                                      pWh2, pWl2, pWh2, pWl2, pWh2, pWl2,
                                      b2, b2, b2, pS, pS, pS,
                                      pS, NTOK, D_MODEL, D_FF);
    }

    ln_kernel<0><<<NTOK/8, 256>>>(pS, pY, nullptr, fn_g, fn_b);
    ulong_kernel<<<BATCH, 256>>>(user_emb, us);
    gate_kernel<<<BATCH/8, 256>>>(gWl, gWs, gWt, gbias, time_emb, tdl);
    score_kernel<<<dim3(BATCH, 4), 256>>>(item_emb, pred, out);
}

// round 15
// speedup vs baseline: 1.1135x; 1.1135x over previous
#include <cuda_runtime.h>
#include <math.h>

#define D_MODEL 256
#define NHEAD 8
#define DHEAD 32
#define D_FF 1024
#define N_BLOCKS 2
#define BATCH 256
#define INTER 50
#define INTRA 20
#define CAND 2048
#define NTOK (BATCH*INTER)
#define NEG_INF -1.0e9f

// ---------------- scratch (device globals; allocation-free) ----------------
__device__ __align__(256) float g_Ehat[NTOK*D_MODEL];
__device__ __align__(256) float g_S [NTOK*D_MODEL];
__device__ __align__(256) float g_Yb [NTOK*D_MODEL];
__device__ __align__(256) float g_Qb [NTOK*D_MODEL];
__device__ __align__(256) float g_Kb [NTOK*D_MODEL];
__device__ __align__(256) float g_Vb [NTOK*D_MODEL];
__device__ __align__(256) float g_Tb [NTOK*D_MODEL];
__device__ __align__(256) float g_Hb [NTOK*D_FF];
__device__ __align__(256) float g_ushort[BATCH*D_MODEL];
__device__ __align__(256) float g_ulong [BATCH*D_MODEL];
__device__ __align__(256) float g_Ugate [BATCH*D_MODEL];
// transposed fp32 weights [N][K]
__device__ __align__(256) float g_Wtq[D_MODEL*D_MODEL];
__device__ __align__(256) float g_Wtk[D_MODEL*D_MODEL];
__device__ __align__(256) float g_Wtv[D_MODEL*D_MODEL];
__device__ __align__(256) float g_Wto[D_MODEL*D_MODEL];
__device__ __align__(256) float g_Wt1[D_MODEL*D_FF];
__device__ __align__(256) float g_Wt2[D_FF*D_MODEL];

// ---------------- tf32 / mma / cp.async helpers ----------------
__device__ __forceinline__ unsigned f2tf32(float f) {
    unsigned u; asm("cvt.rna.tf32.f32 %0, %1;" : "=r"(u) : "f"(f)); return u;
}
__device__ __forceinline__ void split_tf32u(float v, unsigned &hi, unsigned &lo) {
    hi = f2tf32(v);
    lo = f2tf32(v - __uint_as_float(hi));
}
__device__ __forceinline__ void mma_tf32(float* c,
    unsigned a0, unsigned a1, unsigned a2, unsigned a3,
    unsigned b0, unsigned b1) {
    asm volatile("mma.sync.aligned.m16n8k8.row.col.f32.tf32.tf32.f32 "
        "{%0,%1,%2,%3}, {%4,%5,%6,%7}, {%8,%9}, {%0,%1,%2,%3};"
        : "+f"(c[0]), "+f"(c[1]), "+f"(c[2]), "+f"(c[3])
        : "r"(a0), "r"(a1), "r"(a2), "r"(a3), "r"(b0), "r"(b1));
}
__device__ __forceinline__ void cp16(void* smem, const void* g) {
    unsigned s = (unsigned)__cvta_generic_to_shared(smem);
    asm volatile("cp.async.cg.shared.global [%0], [%1], 16;" :: "r"(s), "l"(g));
}
__device__ __forceinline__ void cp_commit() {
    asm volatile("cp.async.commit_group;" ::: "memory");
}
__device__ __forceinline__ void cp_wait0() {
    asm volatile("cp.async.wait_group 0;" ::: "memory");
}

// ---------------- weight transpose (fp32): W[K][N] -> Wt[N][K] ----------------
__global__ __launch_bounds__(256) void transpose_k(const float* __restrict__ W,
                                                   float* __restrict__ Wt,
                                                   int Kd, int Nd) {
    __shared__ float tile[32][33];
    const int n0 = blockIdx.x*32, k0 = blockIdx.y*32;
    const int tx = threadIdx.x & 31, ty = threadIdx.x >> 5;
    #pragma unroll
    for (int i = 0; i < 4; i++) {
        int r = ty + i*8;
        tile[r][tx] = W[(size_t)(k0+r)*Nd + n0 + tx];
    }
    __syncthreads();
    #pragma unroll
    for (int i = 0; i < 4; i++) {
        int r = ty + i*8;
        Wt[(size_t)(n0+r)*Kd + k0 + tx] = tile[tx][r];
    }
}

// ---------------- 3xTF32 tensor-core GEMM: C = A@W + bias (+relu | +res) ----------------
// CTA 64(M)x64(N), 128 threads (2x2 warps), warp tile 32x32, BK=32,
// cp.async double buffer, in-fragment hi/lo split (fp32 tiles in smem).
template<int MODE>   // 0: bias (z selects triple), 1: bias+relu, 2: bias+residual
__global__ __launch_bounds__(128) void tf32gemm(
    const float* __restrict__ A,
    const float* __restrict__ Wta, const float* __restrict__ Wtb, const float* __restrict__ Wtc,
    const float* __restrict__ ba,  const float* __restrict__ bb,  const float* __restrict__ bc,
    float* __restrict__ Ca, float* __restrict__ Cb, float* __restrict__ Cc,
    const float* __restrict__ res, int M, int N, int K) {
    __shared__ float As[2][64][36];
    __shared__ float Bs[2][64][36];

    const float* Wt = Wta; const float* bias = ba; float* C = Ca;
    if (MODE == 0) {
        if (blockIdx.z == 1) { Wt = Wtb; bias = bb; C = Cb; }
        else if (blockIdx.z == 2) { Wt = Wtc; bias = bc; C = Cc; }
    }

    const int t = threadIdx.x;
    const int wid = t >> 5, lane = t & 31;
    const int wm = wid & 1, wn = wid >> 1;          // 2x2 warp grid
    const int gid = lane >> 2, tig = lane & 3;
    const int bm = blockIdx.y * 64, bn = blockIdx.x * 64;
    const int lm = t >> 3, lc = t & 7;              // loader: 16 rows x 8 chunks

    float acc[2][4][4];
    #pragma unroll
    for (int i = 0; i < 2; i++)
        #pragma unroll
        for (int j = 0; j < 4; j++)
            #pragma unroll
            for (int k = 0; k < 4; k++) acc[i][j][k] = 0.f;

    const int nKB = K >> 5;
    auto issue = [&](int buf, int k0) {
        #pragma unroll
        for (int i = 0; i < 4; i++) {
            int m = lm + i*16;
            cp16(&As[buf][m][lc*4], A  + (size_t)(bm+m)*K + k0 + lc*4);
            cp16(&Bs[buf][m][lc*4], Wt + (size_t)(bn+m)*K + k0 + lc*4);
        }
        cp_commit();
    };

    issue(0, 0);
    for (int kb = 0; kb < nKB; kb++) {
        const int cur = kb & 1;
        cp_wait0();
        __syncthreads();
        if (kb + 1 < nKB) issue(cur ^ 1, (kb+1)*32);
        #pragma unroll
        for (int j = 0; j < 4; j++) {
            unsigned ah[2][4], al[2][4], bh[4][2], bl[4][2];
            #pragma unroll
            for (int mt = 0; mt < 2; mt++) {
                int r = wm*32 + mt*16 + gid;
                split_tf32u(As[cur][r  ][8*j + tig],     ah[mt][0], al[mt][0]);
                split_tf32u(As[cur][r+8][8*j + tig],     ah[mt][1], al[mt][1]);
                split_tf32u(As[cur][r  ][8*j + 4 + tig], ah[mt][2], al[mt][2]);
                split_tf32u(As[cur][r+8][8*j + 4 + tig], ah[mt][3], al[mt][3]);
            }
            #pragma unroll
            for (int nt = 0; nt < 4; nt++) {
                int n = wn*32 + nt*8 + gid;
                split_tf32u(Bs[cur][n][8*j + tig],     bh[nt][0], bl[nt][0]);
                split_tf32u(Bs[cur][n][8*j + 4 + tig], bh[nt][1], bl[nt][1]);
            }
            #pragma unroll
            for (int mt = 0; mt < 2; mt++)
                #pragma unroll
                for (int nt = 0; nt < 4; nt++) {
                    mma_tf32(acc[mt][nt], al[mt][0], al[mt][1], al[mt][2], al[mt][3],
                             bh[nt][0], bh[nt][1]);
                    mma_tf32(acc[mt][nt], ah[mt][0], ah[mt][1], ah[mt][2], ah[mt][3],
                             bl[nt][0], bl[nt][1]);
                    mma_tf32(acc[mt][nt], ah[mt][0], ah[mt][1], ah[mt][2], ah[mt][3],
                             bh[nt][0], bh[nt][1]);
                }
        }
        __syncthreads();
    }

    // epilogue
    #pragma unroll
    for (int nt = 0; nt < 4; nt++) {
        const int col = bn + wn*32 + nt*8 + 2*tig;
        const float2 bb2 = *(const float2*)(bias + col);
        #pragma unroll
        for (int mt = 0; mt < 2; mt++) {
            #pragma unroll
            for (int h = 0; h < 2; h++) {
                const int row = bm + wm*32 + mt*16 + gid + h*8;
                float v0 = acc[mt][nt][h*2+0] + bb2.x;
                float v1 = acc[mt][nt][h*2+1] + bb2.y;
                if (MODE == 1) { v0 = fmaxf(v0, 0.f); v1 = fmaxf(v1, 0.f); }
                if (MODE == 2) {
                    float2 r2 = *(const float2*)(res + (size_t)row*N + col);
                    v0 += r2.x; v1 += r2.y;
                }
                float2 o; o.x = v0; o.y = v1;
                *(float2*)(C + (size_t)row*N + col) = o;
            }
        }
    }
}

// ---------------- intra-session attention -> E_hat ----------------
__global__ __launch_bounds__(128) void intra_kernel(const float* __restrict__ item_emb,
                                                    const int* __restrict__ sessions) {
    __shared__ float x[INTRA][260];
    __shared__ float sc[INTRA][INTRA+1];
    __shared__ float wsum[INTRA];
    __shared__ int   idxs[INTRA];
    const int n = blockIdx.x;
    const int t = threadIdx.x;

    if (t < INTRA) idxs[t] = sessions[n*INTRA + t];
    __syncthreads();

    for (int j = t; j < INTRA*64; j += 128) {
        int r = j >> 6, c = j & 63;
        float4 v = make_float4(0.f,0.f,0.f,0.f);
        int idx = idxs[r];
        if (idx != 0) v = *(const float4*)(item_emb + (size_t)idx*D_MODEL + c*4);
        *(float4*)&x[r][c*4] = v;
    }
    __syncthreads();

    if (t < 80) {
        const int qp = t >> 3, c = t & 7;
        const unsigned mask = (t >= 64) ? 0x0000ffffu : 0xffffffffu;
        float4 qA[8], qB[8];
        #pragma unroll
        for (int i = 0; i < 8; i++) {
            qA[i] = *(const float4*)&x[2*qp  ][c*32 + i*4];
            qB[i] = *(const float4*)&x[2*qp+1][c*32 + i*4];
        }
        for (int k = 0; k < INTRA; k++) {
            float sa = 0.f, sb = 0.f;
            #pragma unroll
            for (int i = 0; i < 8; i++) {
                float4 bv = *(const float4*)&x[k][c*32 + i*4];
                sa += qA[i].x*bv.x + qA[i].y*bv.y + qA[i].z*bv.z + qA[i].w*bv.w;
                sb += qB[i].x*bv.x + qB[i].y*bv.y + qB[i].z*bv.z + qB[i].w*bv.w;
            }
            sa += __shfl_xor_sync(mask, sa, 1);
            sa += __shfl_xor_sync(mask, sa, 2);
            sa += __shfl_xor_sync(mask, sa, 4);
            sb += __shfl_xor_sync(mask, sb, 1);
            sb += __shfl_xor_sync(mask, sb, 2);
            sb += __shfl_xor_sync(mask, sb, 4);
            if (c == 0) {
                sc[2*qp  ][k] = sa * 0.0625f;
                sc[2*qp+1][k] = sb * 0.0625f;
            }
        }
    }
    __syncthreads();

    if (t < INTRA) {
        float v[INTRA];
        float mx = -3.0e38f;
        #pragma unroll
        for (int k = 0; k < INTRA; k++) {
            float s = (idxs[k] != 0) ? sc[t][k] : NEG_INF;
            v[k] = s; mx = fmaxf(mx, s);
        }
        float sum = 0.f;
        #pragma unroll
        for (int k = 0; k < INTRA; k++) { float e = __expf(v[k]-mx); v[k] = e; sum += e; }
        float inv = 1.f/sum;
        #pragma unroll
        for (int k = 0; k < INTRA; k++) sc[t][k] = v[k]*inv;
    }
    __syncthreads();

    if (t < INTRA) {
        float w = 0.f;
        #pragma unroll
        for (int q = 0; q < INTRA; q++) w += sc[q][t];
        wsum[t] = w;
    }
    __syncthreads();

    float* outp = g_Ehat + (size_t)n*D_MODEL;
    for (int d = t; d < D_MODEL; d += 128) {
        float acc = 0.f;
        #pragma unroll
        for (int k = 0; k < INTRA; k++) acc += wsum[k]*x[k][d];
        outp[d] = acc;
    }
}

// ---------------- S = E_hat + PE ; u_short ----------------
__global__ __launch_bounds__(256) void initS_kernel() {
    int i = blockIdx.x*256 + threadIdx.x;
    int d = i & 255;
    int tok = i >> 8;
    int pos = tok % INTER;
    int j = d >> 1;
    float div = expf((float)(2*j) * (-0.03597789207803197f));
    float ang = (float)pos * div;
    float pe = (d & 1) ? cosf(ang) : sinf(ang);
    float eh = g_Ehat[i];
    g_S[i] = eh + pe;
    if (pos == INTER-1) g_ushort[(tok/INTER)*D_MODEL + d] = eh;
}

// ---------------- LayerNorm ----------------
__global__ __launch_bounds__(256) void ln_kernel(const float* __restrict__ x, float* __restrict__ y,
                                                 const float* __restrict__ g, const float* __restrict__ b) {
    const int tok  = blockIdx.x*8 + (threadIdx.x >> 5);
    const int lane = threadIdx.x & 31;
    const float4* xr = (const float4*)(x + (size_t)tok*D_MODEL);
    float4 a = xr[lane*2], c = xr[lane*2+1];
    float s  = a.x+a.y+a.z+a.w + c.x+c.y+c.z+c.w;
    float ss = a.x*a.x+a.y*a.y+a.z*a.z+a.w*a.w + c.x*c.x+c.y*c.y+c.z*c.z+c.w*c.w;
    #pragma unroll
    for (int o = 16; o > 0; o >>= 1) {
        s  += __shfl_xor_sync(0xffffffffu, s , o);
        ss += __shfl_xor_sync(0xffffffffu, ss, o);
    }
    float m   = s * (1.f/256.f);
    float var = fmaxf((ss - 256.f*m*m) * (1.f/255.f), 0.f);
    float inv = 1.f/(sqrtf(var) + 1e-6f);
    float4 g0 = ((const float4*)g)[lane*2], g1 = ((const float4*)g)[lane*2+1];
    float4 b0 = ((const float4*)b)[lane*2], b1 = ((const float4*)b)[lane*2+1];
    float4 o0, o1;
    o0.x = g0.x*(a.x-m)*inv + b0.x;  o0.y = g0.y*(a.y-m)*inv + b0.y;
    o0.z = g0.z*(a.z-m)*inv + b0.z;  o0.w = g0.w*(a.w-m)*inv + b0.w;
    o1.x = g1.x*(c.x-m)*inv + b1.x;  o1.y = g1.y*(c.y-m)*inv + b1.y;
    o1.z = g1.z*(c.z-m)*inv + b1.z;  o1.w = g1.w*(c.w-m)*inv + b1.w;
    float4* yr = (float4*)(y + (size_t)tok*D_MODEL);
    yr[lane*2] = o0; yr[lane*2+1] = o1;
}

// ---------------- inter attention: per (batch, head) ----------------
__global__ __launch_bounds__(128) void attn_kernel(const int* __restrict__ sessions) {
    const int b = blockIdx.x, h = blockIdx.y;
    __shared__ float ks[INTER][36];
    __shared__ float vs[INTER][36];
    __shared__ float sc[INTER][53];
    __shared__ int   valid[INTER];
    const int t = threadIdx.x;

    if (t < INTER) valid[t] = sessions[(size_t)(b*INTER + t)*INTRA];
    const float* Kb = g_Kb + (size_t)b*INTER*D_MODEL + h*DHEAD;
    const float* Vb = g_Vb + (size_t)b*INTER*D_MODEL + h*DHEAD;
    for (int j = t; j < INTER*8; j += 128) {
        int r = j >> 3, c = j & 7;
        *(float4*)&ks[r][c*4] = *(const float4*)(Kb + (size_t)r*D_MODEL + c*4);
        *(float4*)&vs[r][c*4] = *(const float4*)(Vb + (size_t)r*D_MODEL + c*4);
    }
    __syncthreads();

    if (t < INTER) {
        const float* Qr = g_Qb + (size_t)(b*INTER + t)*D_MODEL + h*DHEAD;
        float4 q[8];
        #pragma unroll
        for (int i = 0; i < 8; i++) q[i] = *(const float4*)(Qr + i*4);
        float mx = -3.0e38f;
        for (int k = 0; k < INTER; k++) {
            float s = 0.f;
            #pragma unroll
            for (int i = 0; i < 8; i++) {
                float4 kv = *(const float4*)&ks[k][i*4];
                s += q[i].x*kv.x + q[i].y*kv.y + q[i].z*kv.z + q[i].w*kv.w;
            }
            s = (valid[k] != 0) ? s*0.17677669529663688f : NEG_INF;
            sc[t][k] = s; mx = fmaxf(mx, s);
        }
        float sum = 0.f;
        for (int k = 0; k < INTER; k++) { float e = __expf(sc[t][k]-mx); sc[t][k] = e; sum += e; }
        float inv = 1.f/sum;
        for (int k = 0; k < INTER; k++) sc[t][k] *= inv;
    }
    __syncthreads();

    float* Ob = g_Tb + (size_t)b*INTER*D_MODEL + h*DHEAD;
    for (int e = t; e < INTER*DHEAD; e += 128) {
        int q = e >> 5, d = e & 31;
        float acc = 0.f;
        #pragma unroll 10
        for (int k = 0; k < INTER; k++) acc += sc[q][k]*vs[k][d];
        Ob[(size_t)q*D_MODEL + d] = acc;
    }
}

// ---------------- u_long ----------------
__global__ __launch_bounds__(256) void ulong_kernel(const float* __restrict__ user_emb,
                                                    const int* __restrict__ us) {
    const int b = blockIdx.x, d = threadIdx.x;
    float acc = 0.f;
    const float* Yb = g_Yb + (size_t)b*INTER*D_MODEL + d;
    #pragma unroll 10
    for (int i = 0; i < INTER; i++) acc += Yb[(size_t)i*D_MODEL];
    g_ulong[b*D_MODEL + d] = acc + user_emb[(size_t)us[b]*D_MODEL + d];
}

// ---------------- gate + fuse ----------------
__global__ __launch_bounds__(256) void gate_kernel(
    const float* __restrict__ Wl, const float* __restrict__ Ws,
    const float* __restrict__ Wt, const float* __restrict__ gb,
    const float* __restrict__ time_emb, const int* __restrict__ tdl) {
    __shared__ float ul[8][260], uss[8][260], te[8][260];
    const int t = threadIdx.x;
    const int b0 = blockIdx.x*8;
    for (int j = t; j < 8*64; j += 256) {
        int bi = j >> 6, c = j & 63;
        *(float4*)&ul [bi][c*4] = *(const float4*)(g_ulong  + (size_t)(b0+bi)*D_MODEL + c*4);
        *(float4*)&uss[bi][c*4] = *(const float4*)(g_ushort + (size_t)(b0+bi)*D_MODEL + c*4);
        *(float4*)&te [bi][c*4] = *(const float4*)(time_emb + (size_t)tdl[b0+bi]*D_MODEL + c*4);
    }
    __syncthreads();
    const int d = t;
    float acc[8] = {0.f,0.f,0.f,0.f,0.f,0.f,0.f,0.f};
    for (int k = 0; k < D_MODEL; k++) {
        float wl = Wl[(size_t)k*D_MODEL + d];
        float ws = Ws[(size_t)k*D_MODEL + d];
        float wt = Wt[(size_t)k*D_MODEL + d];
        #pragma unroll
        for (int bi = 0; bi < 8; bi++)
            acc[bi] += ul[bi][k]*wl + uss[bi][k]*ws + te[bi][k]*wt;
    }
    float gbv = gb[d];
    #pragma unroll
    for (int bi = 0; bi < 8; bi++) {
        float z  = acc[bi] + gbv;
        float tg = 1.f/(1.f + expf(-z));
        g_Ugate[(size_t)(b0+bi)*D_MODEL + d] = tg*uss[bi][d] + (1.f-tg)*ul[bi][d];
    }
}

// ---------------- candidate scoring ----------------
__global__ __launch_bounds__(256) void score_kernel(const float* __restrict__ item_emb,
                                                    const int* __restrict__ pred,
                                                    float* __restrict__ out) {
    const int b = blockIdx.x;
    const int warp = threadIdx.x >> 5, lane = threadIdx.x & 31;
    const int wg = blockIdx.y*8 + warp;
    const float4* up = (const float4*)(g_Ugate + (size_t)b*D_MODEL);
    float4 ua = up[lane*2], ub = up[lane*2+1];
    const int cbase = b*CAND;
    for (int c0 = wg*64; c0 < wg*64 + 64; c0 += 2) {
        int i0 = pred[cbase + c0];
        int i1 = pred[cbase + c0 + 1];
        const float4* r0 = (const float4*)(item_emb + (size_t)i0*D_MODEL);
        const float4* r1 = (const float4*)(item_emb + (size_t)i1*D_MODEL);
        float4 a0 = r0[lane*2], b0 = r0[lane*2+1];
        float4 a1 = r1[lane*2], b1 = r1[lane*2+1];
        float s0 = a0.x*ua.x + a0.y*ua.y + a0.z*ua.z + a0.w*ua.w
                 + b0.x*ub.x + b0.y*ub.y + b0.z*ub.z + b0.w*ub.w;
        float s1 = a1.x*ua.x + a1.y*ua.y + a1.z*ua.z + a1.w*ua.w
                 + b1.x*ub.x + b1.y*ub.y + b1.z*ub.z + b1.w*ub.w;
        #pragma unroll
        for (int o = 16; o > 0; o >>= 1) {
            s0 += __shfl_xor_sync(0xffffffffu, s0, o);
            s1 += __shfl_xor_sync(0xffffffffu, s1, o);
        }
        if (lane == 0) {
            out[(size_t)cbase + c0]     = s0;
            out[(size_t)cbase + c0 + 1] = s1;
        }
    }
}

// ---------------- launcher ----------------
extern "C" void kernel_launch(void* const* d_in, const int* in_sizes, int n_in,
                              void* d_out, int out_size) {
    (void)in_sizes; (void)n_in; (void)out_size;
    const float* item_emb = (const float*)d_in[0];
    const float* user_emb = (const float*)d_in[1];
    const float* time_emb = (const float*)d_in[2];
    const float* Wq = (const float*)d_in[3];   const float* bq = (const float*)d_in[4];
    const float* Wk = (const float*)d_in[5];   const float* bk = (const float*)d_in[6];
    const float* Wv = (const float*)d_in[7];   const float* bv = (const float*)d_in[8];
    const float* Wo = (const float*)d_in[9];   const float* bo = (const float*)d_in[10];
    const float* ln1_g = (const float*)d_in[11]; const float* ln1_b = (const float*)d_in[12];
    const float* W1 = (const float*)d_in[13];  const float* b1 = (const float*)d_in[14];
    const float* W2 = (const float*)d_in[15];  const float* b2 = (const float*)d_in[16];
    const float* ln2_g = (const float*)d_in[17]; const float* ln2_b = (const float*)d_in[18];
    const float* fn_g  = (const float*)d_in[19]; const float* fn_b  = (const float*)d_in[20];
    const float* gWl = (const float*)d_in[21]; const float* gWs = (const float*)d_in[22];
    const float* gWt = (const float*)d_in[23]; const float* gbias = (const float*)d_in[24];
    const int* us   = (const int*)d_in[25];
    const int* sess = (const int*)d_in[26];
    const int* tdl  = (const int*)d_in[27];
    const int* pred = (const int*)d_in[28];
    float* out = (float*)d_out;

    float *pS, *pY, *pQ, *pK, *pV, *pT, *pH;
    float *pWtq, *pWtk, *pWtv, *pWto, *pWt1, *pWt2;
    cudaGetSymbolAddress((void**)&pS, g_S);
    cudaGetSymbolAddress((void**)&pY, g_Yb);
    cudaGetSymbolAddress((void**)&pQ, g_Qb);
    cudaGetSymbolAddress((void**)&pK, g_Kb);
    cudaGetSymbolAddress((void**)&pV, g_Vb);
    cudaGetSymbolAddress((void**)&pT, g_Tb);
    cudaGetSymbolAddress((void**)&pH, g_Hb);
    cudaGetSymbolAddress((void**)&pWtq, g_Wtq);
    cudaGetSymbolAddress((void**)&pWtk, g_Wtk);
    cudaGetSymbolAddress((void**)&pWtv, g_Wtv);
    cudaGetSymbolAddress((void**)&pWto, g_Wto);
    cudaGetSymbolAddress((void**)&pWt1, g_Wt1);
    cudaGetSymbolAddress((void**)&pWt2, g_Wt2);

    // one-time (per launch) fp32 weight transpose
    transpose_k<<<dim3(8,8),  256>>>(Wq, pWtq, D_MODEL, D_MODEL);
    transpose_k<<<dim3(8,8),  256>>>(Wk, pWtk, D_MODEL, D_MODEL);
    transpose_k<<<dim3(8,8),  256>>>(Wv, pWtv, D_MODEL, D_MODEL);
    transpose_k<<<dim3(8,8),  256>>>(Wo, pWto, D_MODEL, D_MODEL);
    transpose_k<<<dim3(32,8), 256>>>(W1, pWt1, D_MODEL, D_FF);
    transpose_k<<<dim3(8,32), 256>>>(W2, pWt2, D_FF, D_MODEL);

    intra_kernel<<<NTOK, 128>>>(item_emb, sess);
    initS_kernel<<<NTOK*D_MODEL/256, 256>>>();

    const dim3 gQKV(D_MODEL/64, NTOK/64, 3);   // (4, 40, 3)
    const dim3 gO  (D_MODEL/64, NTOK/64, 1);
    const dim3 gF1 (D_FF/64,   NTOK/64, 1);
    const dim3 gF2 (D_MODEL/64, NTOK/64, 1);

    for (int blk = 0; blk < N_BLOCKS; blk++) {
        ln_kernel<<<NTOK/8, 256>>>(pS, pY, ln1_g, ln1_b);
        tf32gemm<0><<<gQKV, 128>>>(pY, pWtq, pWtk, pWtv, bq, bk, bv,
                                   pQ, pK, pV, nullptr, NTOK, D_MODEL, D_MODEL);
        attn_kernel<<<dim3(BATCH, NHEAD), 128>>>(sess);
        tf32gemm<2><<<gO, 128>>>(pT, pWto, pWto, pWto, bo, bo, bo,
                                 pS, pS, pS, pS, NTOK, D_MODEL, D_MODEL);
        ln_kernel<<<NTOK/8, 256>>>(pS, pY, ln2_g, ln2_b);
        tf32gemm<1><<<gF1, 128>>>(pY, pWt1, pWt1, pWt1, b1, b1, b1,
                                  pH, pH, pH, nullptr, NTOK, D_FF, D_MODEL);
        tf32gemm<2><<<gF2, 128>>>(pH, pWt2, pWt2, pWt2, b2, b2, b2,
                                  pS, pS, pS, pS, NTOK, D_MODEL, D_FF);
    }

    ln_kernel<<<NTOK/8, 256>>>(pS, pY, fn_g, fn_b);
    ulong_kernel<<<BATCH, 256>>>(user_emb, us);
    gate_kernel<<<BATCH/8, 256>>>(gWl, gWs, gWt, gbias, time_emb, tdl);
    score_kernel<<<dim3(BATCH, 4), 256>>>(item_emb, pred, out);
}

// round 17
// speedup vs baseline: 1.1187x; 1.0047x over previous
#include <cuda_runtime.h>
#include <math.h>

#define D_MODEL 256
#define NHEAD 8
#define DHEAD 32
#define D_FF 1024
#define N_BLOCKS 2
#define BATCH 256
#define INTER 50
#define INTRA 20
#define CAND 2048
#define NTOK (BATCH*INTER)
#define NEG_INF -1.0e9f

// ---------------- scratch (device globals; allocation-free) ----------------
__device__ __align__(256) float g_S [NTOK*D_MODEL];
__device__ __align__(256) float g_Yb [NTOK*D_MODEL];
__device__ __align__(256) float g_Qb [NTOK*D_MODEL];
__device__ __align__(256) float g_Kb [NTOK*D_MODEL];
__device__ __align__(256) float g_Vb [NTOK*D_MODEL];
__device__ __align__(256) float g_Tb [NTOK*D_MODEL];
__device__ __align__(256) float g_Hb [NTOK*D_FF];
__device__ __align__(256) float g_PE [INTER*D_MODEL];
__device__ __align__(256) float g_ushort[BATCH*D_MODEL];
__device__ __align__(256) float g_ulong [BATCH*D_MODEL];
__device__ __align__(256) float g_Ugate [BATCH*D_MODEL];
// transposed fp32 weights [N][K]
__device__ __align__(256) float g_Wtq[D_MODEL*D_MODEL];
__device__ __align__(256) float g_Wtk[D_MODEL*D_MODEL];
__device__ __align__(256) float g_Wtv[D_MODEL*D_MODEL];
__device__ __align__(256) float g_Wto[D_MODEL*D_MODEL];
__device__ __align__(256) float g_Wt1[D_MODEL*D_FF];
__device__ __align__(256) float g_Wt2[D_FF*D_MODEL];

// ---------------- tf32 / mma / cp.async helpers ----------------
__device__ __forceinline__ unsigned f2tf32(float f) {
    unsigned u; asm("cvt.rna.tf32.f32 %0, %1;" : "=r"(u) : "f"(f)); return u;
}
__device__ __forceinline__ void split_tf32u(float v, unsigned &hi, unsigned &lo) {
    hi = f2tf32(v);
    lo = f2tf32(v - __uint_as_float(hi));
}
__device__ __forceinline__ void mma_tf32(float* c,
    unsigned a0, unsigned a1, unsigned a2, unsigned a3,
    unsigned b0, unsigned b1) {
    asm volatile("mma.sync.aligned.m16n8k8.row.col.f32.tf32.tf32.f32 "
        "{%0,%1,%2,%3}, {%4,%5,%6,%7}, {%8,%9}, {%0,%1,%2,%3};"
        : "+f"(c[0]), "+f"(c[1]), "+f"(c[2]), "+f"(c[3])
        : "r"(a0), "r"(a1), "r"(a2), "r"(a3), "r"(b0), "r"(b1));
}
__device__ __forceinline__ void cp16(void* smem, const void* g) {
    unsigned s = (unsigned)__cvta_generic_to_shared(smem);
    asm volatile("cp.async.cg.shared.global [%0], [%1], 16;" :: "r"(s), "l"(g));
}
__device__ __forceinline__ void cp_commit() {
    asm volatile("cp.async.commit_group;" ::: "memory");
}
__device__ __forceinline__ void cp_wait0() {
    asm volatile("cp.async.wait_group 0;" ::: "memory");
}

// ---------------- PE table: g_PE[pos][d] ----------------
__global__ __launch_bounds__(256) void pe_kernel() {
    const int pos = blockIdx.x, d = threadIdx.x;
    int j = d >> 1;
    float div = expf((float)(2*j) * (-0.03597789207803197f));   // -ln(1e4)/256
    float ang = (float)pos * div;
    g_PE[pos*D_MODEL + d] = (d & 1) ? cosf(ang) : sinf(ang);
}

// ---------------- weight transpose (fp32): W[K][N] -> Wt[N][K] ----------------
__global__ __launch_bounds__(256) void transpose_k(const float* __restrict__ W,
                                                   float* __restrict__ Wt,
                                                   int Kd, int Nd) {
    __shared__ float tile[32][33];
    const int n0 = blockIdx.x*32, k0 = blockIdx.y*32;
    const int tx = threadIdx.x & 31, ty = threadIdx.x >> 5;
    #pragma unroll
    for (int i = 0; i < 4; i++) {
        int r = ty + i*8;
        tile[r][tx] = W[(size_t)(k0+r)*Nd + n0 + tx];
    }
    __syncthreads();
    #pragma unroll
    for (int i = 0; i < 4; i++) {
        int r = ty + i*8;
        Wt[(size_t)(n0+r)*Kd + k0 + tx] = tile[tx][r];
    }
}

// ---------------- 3xTF32 tensor-core GEMM (R15-verified) ----------------
template<int MODE>   // 0: bias (z selects triple), 1: bias+relu, 2: bias+residual
__global__ __launch_bounds__(128) void tf32gemm(
    const float* __restrict__ A,
    const float* __restrict__ Wta, const float* __restrict__ Wtb, const float* __restrict__ Wtc,
    const float* __restrict__ ba,  const float* __restrict__ bb,  const float* __restrict__ bc,
    float* __restrict__ Ca, float* __restrict__ Cb, float* __restrict__ Cc,
    const float* __restrict__ res, int M, int N, int K) {
    __shared__ float As[2][64][36];
    __shared__ float Bs[2][64][36];

    const float* Wt = Wta; const float* bias = ba; float* C = Ca;
    if (MODE == 0) {
        if (blockIdx.z == 1) { Wt = Wtb; bias = bb; C = Cb; }
        else if (blockIdx.z == 2) { Wt = Wtc; bias = bc; C = Cc; }
    }

    const int t = threadIdx.x;
    const int wid = t >> 5, lane = t & 31;
    const int wm = wid & 1, wn = wid >> 1;
    const int gid = lane >> 2, tig = lane & 3;
    const int bm = blockIdx.y * 64, bn = blockIdx.x * 64;
    const int lm = t >> 3, lc = t & 7;

    float acc[2][4][4];
    #pragma unroll
    for (int i = 0; i < 2; i++)
        #pragma unroll
        for (int j = 0; j < 4; j++)
            #pragma unroll
            for (int k = 0; k < 4; k++) acc[i][j][k] = 0.f;

    const int nKB = K >> 5;
    auto issue = [&](int buf, int k0) {
        #pragma unroll
        for (int i = 0; i < 4; i++) {
            int m = lm + i*16;
            cp16(&As[buf][m][lc*4], A  + (size_t)(bm+m)*K + k0 + lc*4);
            cp16(&Bs[buf][m][lc*4], Wt + (size_t)(bn+m)*K + k0 + lc*4);
        }
        cp_commit();
    };

    issue(0, 0);
    for (int kb = 0; kb < nKB; kb++) {
        const int cur = kb & 1;
        cp_wait0();
        __syncthreads();
        if (kb + 1 < nKB) issue(cur ^ 1, (kb+1)*32);
        #pragma unroll
        for (int j = 0; j < 4; j++) {
            unsigned ah[2][4], al[2][4], bh[4][2], bl[4][2];
            #pragma unroll
            for (int mt = 0; mt < 2; mt++) {
                int r = wm*32 + mt*16 + gid;
                split_tf32u(As[cur][r  ][8*j + tig],     ah[mt][0], al[mt][0]);
                split_tf32u(As[cur][r+8][8*j + tig],     ah[mt][1], al[mt][1]);
                split_tf32u(As[cur][r  ][8*j + 4 + tig], ah[mt][2], al[mt][2]);
                split_tf32u(As[cur][r+8][8*j + 4 + tig], ah[mt][3], al[mt][3]);
            }
            #pragma unroll
            for (int nt = 0; nt < 4; nt++) {
                int n = wn*32 + nt*8 + gid;
                split_tf32u(Bs[cur][n][8*j + tig],     bh[nt][0], bl[nt][0]);
                split_tf32u(Bs[cur][n][8*j + 4 + tig], bh[nt][1], bl[nt][1]);
            }
            #pragma unroll
            for (int mt = 0; mt < 2; mt++)
                #pragma unroll
                for (int nt = 0; nt < 4; nt++) {
                    mma_tf32(acc[mt][nt], al[mt][0], al[mt][1], al[mt][2], al[mt][3],
                             bh[nt][0], bh[nt][1]);
                    mma_tf32(acc[mt][nt], ah[mt][0], ah[mt][1], ah[mt][2], ah[mt][3],
                             bl[nt][0], bl[nt][1]);
                    mma_tf32(acc[mt][nt], ah[mt][0], ah[mt][1], ah[mt][2], ah[mt][3],
                             bh[nt][0], bh[nt][1]);
                }
        }
        __syncthreads();
    }

    #pragma unroll
    for (int nt = 0; nt < 4; nt++) {
        const int col = bn + wn*32 + nt*8 + 2*tig;
        const float2 bb2 = *(const float2*)(bias + col);
        #pragma unroll
        for (int mt = 0; mt < 2; mt++) {
            #pragma unroll
            for (int h = 0; h < 2; h++) {
                const int row = bm + wm*32 + mt*16 + gid + h*8;
                float v0 = acc[mt][nt][h*2+0] + bb2.x;
                float v1 = acc[mt][nt][h*2+1] + bb2.y;
                if (MODE == 1) { v0 = fmaxf(v0, 0.f); v1 = fmaxf(v1, 0.f); }
                if (MODE == 2) {
                    float2 r2 = *(const float2*)(res + (size_t)row*N + col);
                    v0 += r2.x; v1 += r2.y;
                }
                float2 o; o.x = v0; o.y = v1;
                *(float2*)(C + (size_t)row*N + col) = o;
            }
        }
    }
}

// ---------------- intra-session attention -> S = E_hat + PE ; u_short ----------------
__global__ __launch_bounds__(128) void intra_kernel(const float* __restrict__ item_emb,
                                                    const int* __restrict__ sessions) {
    __shared__ float x[INTRA][260];
    __shared__ float sc[INTRA][INTRA+1];
    __shared__ float wsum[INTRA];
    __shared__ int   idxs[INTRA];
    const int n = blockIdx.x;
    const int t = threadIdx.x;

    if (t < INTRA) idxs[t] = sessions[n*INTRA + t];
    __syncthreads();

    for (int j = t; j < INTRA*64; j += 128) {
        int r = j >> 6, c = j & 63;
        float4 v = make_float4(0.f,0.f,0.f,0.f);
        int idx = idxs[r];
        if (idx != 0) v = *(const float4*)(item_emb + (size_t)idx*D_MODEL + c*4);
        *(float4*)&x[r][c*4] = v;
    }
    __syncthreads();

    if (t < 80) {
        const int qp = t >> 3, c = t & 7;
        const unsigned mask = (t >= 64) ? 0x0000ffffu : 0xffffffffu;
        float4 qA[8], qB[8];
        #pragma unroll
        for (int i = 0; i < 8; i++) {
            qA[i] = *(const float4*)&x[2*qp  ][c*32 + i*4];
            qB[i] = *(const float4*)&x[2*qp+1][c*32 + i*4];
        }
        for (int k = 0; k < INTRA; k++) {
            float sa = 0.f, sb = 0.f;
            #pragma unroll
            for (int i = 0; i < 8; i++) {
                float4 bv = *(const float4*)&x[k][c*32 + i*4];
                sa += qA[i].x*bv.x + qA[i].y*bv.y + qA[i].z*bv.z + qA[i].w*bv.w;
                sb += qB[i].x*bv.x + qB[i].y*bv.y + qB[i].z*bv.z + qB[i].w*bv.w;
            }
            sa += __shfl_xor_sync(mask, sa, 1);
            sa += __shfl_xor_sync(mask, sa, 2);
            sa += __shfl_xor_sync(mask, sa, 4);
            sb += __shfl_xor_sync(mask, sb, 1);
            sb += __shfl_xor_sync(mask, sb, 2);
            sb += __shfl_xor_sync(mask, sb, 4);
            if (c == 0) {
                sc[2*qp  ][k] = sa * 0.0625f;
                sc[2*qp+1][k] = sb * 0.0625f;
            }
        }
    }
    __syncthreads();

    if (t < INTRA) {
        float v[INTRA];
        float mx = -3.0e38f;
        #pragma unroll
        for (int k = 0; k < INTRA; k++) {
            float s = (idxs[k] != 0) ? sc[t][k] : NEG_INF;
            v[k] = s; mx = fmaxf(mx, s);
        }
        float sum = 0.f;
        #pragma unroll
        for (int k = 0; k < INTRA; k++) { float e = __expf(v[k]-mx); v[k] = e; sum += e; }
        float inv = 1.f/sum;
        #pragma unroll
        for (int k = 0; k < INTRA; k++) sc[t][k] = v[k]*inv;
    }
    __syncthreads();

    if (t < INTRA) {
        float w = 0.f;
        #pragma unroll
        for (int q = 0; q < INTRA; q++) w += sc[q][t];
        wsum[t] = w;
    }
    __syncthreads();

    // fused epilogue: S = E_hat + PE[pos], u_short when pos == INTER-1
    const int pos = n % INTER;
    float* outS = g_S + (size_t)n*D_MODEL;
    const float* pe = g_PE + pos*D_MODEL;
    float* ush = g_ushort + (size_t)(n/INTER)*D_MODEL;
    for (int d = t; d < D_MODEL; d += 128) {
        float acc = 0.f;
        #pragma unroll
        for (int k = 0; k < INTRA; k++) acc += wsum[k]*x[k][d];
        outS[d] = acc + pe[d];
        if (pos == INTER-1) ush[d] = acc;
    }
}

// ---------------- LayerNorm ----------------
__global__ __launch_bounds__(256) void ln_kernel(const float* __restrict__ x, float* __restrict__ y,
                                                 const float* __restrict__ g, const float* __restrict__ b) {
    const int tok  = blockIdx.x*8 + (threadIdx.x >> 5);
    const int lane = threadIdx.x & 31;
    const float4* xr = (const float4*)(x + (size_t)tok*D_MODEL);
    float4 a = xr[lane*2], c = xr[lane*2+1];
    float s  = a.x+a.y+a.z+a.w + c.x+c.y+c.z+c.w;
    float ss = a.x*a.x+a.y*a.y+a.z*a.z+a.w*a.w + c.x*c.x+c.y*c.y+c.z*c.z+c.w*c.w;
    #pragma unroll
    for (int o = 16; o > 0; o >>= 1) {
        s  += __shfl_xor_sync(0xffffffffu, s , o);
        ss += __shfl_xor_sync(0xffffffffu, ss, o);
    }
    float m   = s * (1.f/256.f);
    float var = fmaxf((ss - 256.f*m*m) * (1.f/255.f), 0.f);
    float inv = 1.f/(sqrtf(var) + 1e-6f);
    float4 g0 = ((const float4*)g)[lane*2], g1 = ((const float4*)g)[lane*2+1];
    float4 b0 = ((const float4*)b)[lane*2], b1 = ((const float4*)b)[lane*2+1];
    float4 o0, o1;
    o0.x = g0.x*(a.x-m)*inv + b0.x;  o0.y = g0.y*(a.y-m)*inv + b0.y;
    o0.z = g0.z*(a.z-m)*inv + b0.z;  o0.w = g0.w*(a.w-m)*inv + b0.w;
    o1.x = g1.x*(c.x-m)*inv + b1.x;  o1.y = g1.y*(c.y-m)*inv + b1.y;
    o1.z = g1.z*(c.z-m)*inv + b1.z;  o1.w = g1.w*(c.w-m)*inv + b1.w;
    float4* yr = (float4*)(y + (size_t)tok*D_MODEL);
    yr[lane*2] = o0; yr[lane*2+1] = o1;
}

// ---------------- inter attention: per (batch, head) ----------------
__global__ __launch_bounds__(128) void attn_kernel(const int* __restrict__ sessions) {
    const int b = blockIdx.x, h = blockIdx.y;
    __shared__ float ks[INTER][36];
    __shared__ float vs[INTER][36];
    __shared__ float sc[INTER][53];
    __shared__ int   valid[INTER];
    const int t = threadIdx.x;

    if (t < INTER) valid[t] = sessions[(size_t)(b*INTER + t)*INTRA];
    const float* Kb = g_Kb + (size_t)b*INTER*D_MODEL + h*DHEAD;
    const float* Vb = g_Vb + (size_t)b*INTER*D_MODEL + h*DHEAD;
    for (int j = t; j < INTER*8; j += 128) {
        int r = j >> 3, c = j & 7;
        *(float4*)&ks[r][c*4] = *(const float4*)(Kb + (size_t)r*D_MODEL + c*4);
        *(float4*)&vs[r][c*4] = *(const float4*)(Vb + (size_t)r*D_MODEL + c*4);
    }
    __syncthreads();

    if (t < INTER) {
        const float* Qr = g_Qb + (size_t)(b*INTER + t)*D_MODEL + h*DHEAD;
        float4 q[8];
        #pragma unroll
        for (int i = 0; i < 8; i++) q[i] = *(const float4*)(Qr + i*4);
        float mx = -3.0e38f;
        for (int k = 0; k < INTER; k++) {
            float s = 0.f;
            #pragma unroll
            for (int i = 0; i < 8; i++) {
                float4 kv = *(const float4*)&ks[k][i*4];
                s += q[i].x*kv.x + q[i].y*kv.y + q[i].z*kv.z + q[i].w*kv.w;
            }
            s = (valid[k] != 0) ? s*0.17677669529663688f : NEG_INF;
            sc[t][k] = s; mx = fmaxf(mx, s);
        }
        float sum = 0.f;
        for (int k = 0; k < INTER; k++) { float e = __expf(sc[t][k]-mx); sc[t][k] = e; sum += e; }
        float inv = 1.f/sum;
        for (int k = 0; k < INTER; k++) sc[t][k] *= inv;
    }
    __syncthreads();

    float* Ob = g_Tb + (size_t)b*INTER*D_MODEL + h*DHEAD;
    for (int e = t; e < INTER*DHEAD; e += 128) {
        int q = e >> 5, d = e & 31;
        float acc = 0.f;
        #pragma unroll 10
        for (int k = 0; k < INTER; k++) acc += sc[q][k]*vs[k][d];
        Ob[(size_t)q*D_MODEL + d] = acc;
    }
}

// ---------------- u_long ----------------
__global__ __launch_bounds__(256) void ulong_kernel(const float* __restrict__ user_emb,
                                                    const int* __restrict__ us) {
    const int b = blockIdx.x, d = threadIdx.x;
    float acc = 0.f;
    const float* Yb = g_Yb + (size_t)b*INTER*D_MODEL + d;
    #pragma unroll 10
    for (int i = 0; i < INTER; i++) acc += Yb[(size_t)i*D_MODEL];
    g_ulong[b*D_MODEL + d] = acc + user_emb[(size_t)us[b]*D_MODEL + d];
}

// ---------------- gate + fuse ----------------
__global__ __launch_bounds__(256) void gate_kernel(
    const float* __restrict__ Wl, const float* __restrict__ Ws,
    const float* __restrict__ Wt, const float* __restrict__ gb,
    const float* __restrict__ time_emb, const int* __restrict__ tdl) {
    __shared__ float ul[8][260], uss[8][260], te[8][260];
    const int t = threadIdx.x;
    const int b0 = blockIdx.x*8;
    for (int j = t; j < 8*64; j += 256) {
        int bi = j >> 6, c = j & 63;
        *(float4*)&ul [bi][c*4] = *(const float4*)(g_ulong  + (size_t)(b0+bi)*D_MODEL + c*4);
        *(float4*)&uss[bi][c*4] = *(const float4*)(g_ushort + (size_t)(b0+bi)*D_MODEL + c*4);
        *(float4*)&te [bi][c*4] = *(const float4*)(time_emb + (size_t)tdl[b0+bi]*D_MODEL + c*4);
    }
    __syncthreads();
    const int d = t;
    float acc[8] = {0.f,0.f,0.f,0.f,0.f,0.f,0.f,0.f};
    for (int k = 0; k < D_MODEL; k++) {
        float wl = Wl[(size_t)k*D_MODEL + d];
        float ws = Ws[(size_t)k*D_MODEL + d];
        float wt = Wt[(size_t)k*D_MODEL + d];
        #pragma unroll
        for (int bi = 0; bi < 8; bi++)
            acc[bi] += ul[bi][k]*wl + uss[bi][k]*ws + te[bi][k]*wt;
    }
    float gbv = gb[d];
    #pragma unroll
    for (int bi = 0; bi < 8; bi++) {
        float z  = acc[bi] + gbv;
        float tg = 1.f/(1.f + expf(-z));
        g_Ugate[(size_t)(b0+bi)*D_MODEL + d] = tg*uss[bi][d] + (1.f-tg)*ul[bi][d];
    }
}

// ---------------- candidate scoring (4-way interleaved) ----------------
__global__ __launch_bounds__(256) void score_kernel(const float* __restrict__ item_emb,
                                                    const int* __restrict__ pred,
                                                    float* __restrict__ out) {
    const int b = blockIdx.x;
    const int warp = threadIdx.x >> 5, lane = threadIdx.x & 31;
    const int wg = blockIdx.y*8 + warp;
    const float4* up = (const float4*)(g_Ugate + (size_t)b*D_MODEL);
    float4 ua = up[lane*2], ub = up[lane*2+1];
    const int cbase = b*CAND;
    for (int c0 = wg*64; c0 < wg*64 + 64; c0 += 4) {
        int idx[4];
        #pragma unroll
        for (int i = 0; i < 4; i++) idx[i] = pred[cbase + c0 + i];
        float s[4];
        #pragma unroll
        for (int i = 0; i < 4; i++) {
            const float4* r = (const float4*)(item_emb + (size_t)idx[i]*D_MODEL);
            float4 a0 = r[lane*2], a1 = r[lane*2+1];
            s[i] = a0.x*ua.x + a0.y*ua.y + a0.z*ua.z + a0.w*ua.w
                 + a1.x*ub.x + a1.y*ub.y + a1.z*ub.z + a1.w*ub.w;
        }
        #pragma unroll
        for (int o = 16; o > 0; o >>= 1) {
            #pragma unroll
            for (int i = 0; i < 4; i++)
                s[i] += __shfl_xor_sync(0xffffffffu, s[i], o);
        }
        if (lane == 0) {
            float4 o4; o4.x = s[0]; o4.y = s[1]; o4.z = s[2]; o4.w = s[3];
            *(float4*)(out + (size_t)cbase + c0) = o4;
        }
    }
}

// ---------------- launcher ----------------
extern "C" void kernel_launch(void* const* d_in, const int* in_sizes, int n_in,
                              void* d_out, int out_size) {
    (void)in_sizes; (void)n_in; (void)out_size;
    const float* item_emb = (const float*)d_in[0];
    const float* user_emb = (const float*)d_in[1];
    const float* time_emb = (const float*)d_in[2];
    const float* Wq = (const float*)d_in[3];   const float* bq = (const float*)d_in[4];
    const float* Wk = (const float*)d_in[5];   const float* bk = (const float*)d_in[6];
    const float* Wv = (const float*)d_in[7];   const float* bv = (const float*)d_in[8];
    const float* Wo = (const float*)d_in[9];   const float* bo = (const float*)d_in[10];
    const float* ln1_g = (const float*)d_in[11]; const float* ln1_b = (const float*)d_in[12];
    const float* W1 = (const float*)d_in[13];  const float* b1 = (const float*)d_in[14];
    const float* W2 = (const float*)d_in[15];  const float* b2 = (const float*)d_in[16];
    const float* ln2_g = (const float*)d_in[17]; const float* ln2_b = (const float*)d_in[18];
    const float* fn_g  = (const float*)d_in[19]; const float* fn_b  = (const float*)d_in[20];
    const float* gWl = (const float*)d_in[21]; const float* gWs = (const float*)d_in[22];
    const float* gWt = (const float*)d_in[23]; const float* gbias = (const float*)d_in[24];
    const int* us   = (const int*)d_in[25];
    const int* sess = (const int*)d_in[26];
    const int* tdl  = (const int*)d_in[27];
    const int* pred = (const int*)d_in[28];
    float* out = (float*)d_out;

    float *pS, *pY, *pQ, *pK, *pV, *pT, *pH;
    float *pWtq, *pWtk, *pWtv, *pWto, *pWt1, *pWt2;
    cudaGetSymbolAddress((void**)&pS, g_S);
    cudaGetSymbolAddress((void**)&pY, g_Yb);
    cudaGetSymbolAddress((void**)&pQ, g_Qb);
    cudaGetSymbolAddress((void**)&pK, g_Kb);
    cudaGetSymbolAddress((void**)&pV, g_Vb);
    cudaGetSymbolAddress((void**)&pT, g_Tb);
    cudaGetSymbolAddress((void**)&pH, g_Hb);
    cudaGetSymbolAddress((void**)&pWtq, g_Wtq);
    cudaGetSymbolAddress((void**)&pWtk, g_Wtk);
    cudaGetSymbolAddress((void**)&pWtv, g_Wtv);
    cudaGetSymbolAddress((void**)&pWto, g_Wto);
    cudaGetSymbolAddress((void**)&pWt1, g_Wt1);
    cudaGetSymbolAddress((void**)&pWt2, g_Wt2);

    // launches 1-5: PE table + 4 transposes; launch 6 = intra (ncu -s 5 -c 1 target)
    pe_kernel<<<INTER, 256>>>();
    transpose_k<<<dim3(8,8),  256>>>(Wq, pWtq, D_MODEL, D_MODEL);
    transpose_k<<<dim3(8,8),  256>>>(Wk, pWtk, D_MODEL, D_MODEL);
    transpose_k<<<dim3(8,8),  256>>>(Wv, pWtv, D_MODEL, D_MODEL);
    transpose_k<<<dim3(8,8),  256>>>(Wo, pWto, D_MODEL, D_MODEL);
    intra_kernel<<<NTOK, 128>>>(item_emb, sess);
    transpose_k<<<dim3(32,8), 256>>>(W1, pWt1, D_MODEL, D_FF);
    transpose_k<<<dim3(8,32), 256>>>(W2, pWt2, D_FF, D_MODEL);

    const dim3 gQKV(D_MODEL/64, NTOK/64, 3);   // (4, 200, 3)
    const dim3 gO  (D_MODEL/64, NTOK/64, 1);
    const dim3 gF1 (D_FF/64,   NTOK/64, 1);
    const dim3 gF2 (D_MODEL/64, NTOK/64, 1);

    for (int blk = 0; blk < N_BLOCKS; blk++) {
        ln_kernel<<<NTOK/8, 256>>>(pS, pY, ln1_g, ln1_b);
        tf32gemm<0><<<gQKV, 128>>>(pY, pWtq, pWtk, pWtv, bq, bk, bv,
                                   pQ, pK, pV, nullptr, NTOK, D_MODEL, D_MODEL);
        attn_kernel<<<dim3(BATCH, NHEAD), 128>>>(sess);
        tf32gemm<2><<<gO, 128>>>(pT, pWto, pWto, pWto, bo, bo, bo,
                                 pS, pS, pS, pS, NTOK, D_MODEL, D_MODEL);
        ln_kernel<<<NTOK/8, 256>>>(pS, pY, ln2_g, ln2_b);
        tf32gemm<1><<<gF1, 128>>>(pY, pWt1, pWt1, pWt1, b1, b1, b1,
                                  pH, pH, pH, nullptr, NTOK, D_FF, D_MODEL);
        tf32gemm<2><<<gF2, 128>>>(pH, pWt2, pWt2, pWt2, b2, b2, b2,
                                  pS, pS, pS, pS, NTOK, D_MODEL, D_FF);
    }

    ln_kernel<<<NTOK/8, 256>>>(pS, pY, fn_g, fn_b);
    ulong_kernel<<<BATCH, 256>>>(user_emb, us);
    gate_kernel<<<BATCH/8, 256>>>(gWl, gWs, gWt, gbias, time_emb, tdl);
    score_kernel<<<dim3(BATCH, 4), 256>>>(item_emb, pred, out);
}